// round 1
// baseline (speedup 1.0000x reference)
#include <cuda_runtime.h>

#define NW       16384
#define MAXLEN   16
#define EMBD     64
#define HIDD     256
#define BW       64          // words per block
#define NTHREADS 512
#define KT       16          // K-tile per stage
#define NST_X    4           // 64/16 stages over x-part
#define NST_H    16          // 256/16 stages over h-part
#define NST      (NST_X + NST_H)

// smem (floats): h double buffer + c + x_t + W double-buffer stage + lengths
#define SMEM_FLOATS (2*BW*HIDD + BW*HIDD + BW*EMBD + 2*KT*128)
#define SMEM_BYTES  (SMEM_FLOATS*4 + BW*4)

__device__ __forceinline__ float fsigm(float x) {
    return __fdividef(1.0f, 1.0f + __expf(-x));
}
__device__ __forceinline__ float ftanh_(float x) {
    return __fdividef(2.0f, 1.0f + __expf(-2.0f * x)) - 1.0f;
}

__global__ __launch_bounds__(NTHREADS, 1)
void bilstm_kernel(const int*   __restrict__ char_ids,
                   const int*   __restrict__ lengths,
                   const float* __restrict__ emb,
                   const float* __restrict__ Wih_f, const float* __restrict__ Whh_f,
                   const float* __restrict__ bih_f, const float* __restrict__ bhh_f,
                   const float* __restrict__ Wih_b, const float* __restrict__ Whh_b,
                   const float* __restrict__ bih_b, const float* __restrict__ bhh_b,
                   float* __restrict__ out)
{
    extern __shared__ float sm[];
    float* h_s  = sm;                    // [2][BW][HIDD]
    float* c_s  = h_s + 2*BW*HIDD;       // [BW][HIDD]
    float* xt_s = c_s + BW*HIDD;         // [BW][EMBD]
    float* W_s  = xt_s + BW*EMBD;        // [2][KT][128]
    int*   len_s = (int*)(W_s + 2*KT*128);  // [BW]

    const int tid  = threadIdx.x;
    const int lane = tid & 31;
    const int warp = tid >> 5;           // 16 warps, each owns 4 words
    const int dir  = blockIdx.y;
    const int w0   = blockIdx.x * BW;

    const float* Wih = dir ? Wih_b : Wih_f;
    const float* Whh = dir ? Whh_b : Whh_f;
    const float* bih = dir ? bih_b : bih_f;
    const float* bhh = dir ? bhh_b : bhh_f;

    // ---- init ----
    for (int i = tid; i < BW; i += NTHREADS) len_s[i] = lengths[w0 + i];
    for (int i = tid; i < 2*BW*HIDD; i += NTHREADS) h_s[i] = 0.0f;
    for (int i = tid; i < BW*HIDD;   i += NTHREADS) c_s[i] = 0.0f;
    __syncthreads();

    // weight-staging constants: 128 rows (4 gates x 32 hid of current chunk),
    // each thread stages 4 consecutive k values of one row (one float4)
    const int rIdx = tid & 127;          // staged row index within chunk
    const int kh   = tid >> 7;           // 0..3 -> k sub-offset
    const int g_st = rIdx >> 5;
    const int i_st = rIdx & 31;

    int cur = 0;
    for (int t = 0; t < MAXLEN; ++t) {
        // ---- gather x_t (embedding lookup, reversed+clipped for backward) ----
        for (int idx = tid; idx < BW*EMBD; idx += NTHREADS) {
            int w = idx >> 6, e = idx & 63;
            int L = len_s[w];
            int te = dir ? max(L - 1 - t, 0) : t;
            int ch = char_ids[(w0 + w)*MAXLEN + te];
            xt_s[idx] = emb[ch*EMBD + e];
        }
        __syncthreads();

        const float* hc = h_s + cur*(BW*HIDD);
        float*       hn = h_s + (cur^1)*(BW*HIDD);

        for (int chunk = 0; chunk < 8; ++chunk) {
            const int j0 = chunk * 32;
            const int row_st = g_st*HIDD + j0 + i_st;   // global weight row for staging

            // accumulators: [gate][word], init with bias (b_ih + b_hh)
            float acc0[4], acc1[4], acc2[4], acc3[4];
            {
                int j = j0 + lane;
                float b0 = bih[j]          + bhh[j];
                float b1 = bih[HIDD + j]   + bhh[HIDD + j];
                float b2 = bih[2*HIDD + j] + bhh[2*HIDD + j];
                float b3 = bih[3*HIDD + j] + bhh[3*HIDD + j];
                #pragma unroll
                for (int wi = 0; wi < 4; ++wi) {
                    acc0[wi] = b0; acc1[wi] = b1; acc2[wi] = b2; acc3[wi] = b3;
                }
            }

            // prefetch stage 0 (x-part weights)
            float4 pf = *(const float4*)(Wih + row_st*EMBD + kh*4);

            for (int s = 0; s < NST; ++s) {
                // commit prefetched tile to smem buffer s&1
                float* wb = W_s + (s & 1)*(KT*128);
                const int kloc = kh * 4;
                wb[(kloc+0)*128 + rIdx] = pf.x;
                wb[(kloc+1)*128 + rIdx] = pf.y;
                wb[(kloc+2)*128 + rIdx] = pf.z;
                wb[(kloc+3)*128 + rIdx] = pf.w;
                __syncthreads();

                // prefetch next stage (overlaps with compute below)
                int sn = s + 1;
                if (sn < NST) {
                    if (sn < NST_X)
                        pf = *(const float4*)(Wih + row_st*EMBD + sn*KT + kh*4);
                    else
                        pf = *(const float4*)(Whh + row_st*HIDD + (sn - NST_X)*KT + kh*4);
                }

                // A-operand row pointers for this stage (warp-uniform -> smem broadcast)
                const float *ar0, *ar1, *ar2, *ar3;
                if (s < NST_X) {
                    const float* base = xt_s + s*KT;
                    ar0 = base + (warp*4+0)*EMBD; ar1 = base + (warp*4+1)*EMBD;
                    ar2 = base + (warp*4+2)*EMBD; ar3 = base + (warp*4+3)*EMBD;
                } else {
                    const float* base = hc + (s - NST_X)*KT;
                    ar0 = base + (warp*4+0)*HIDD; ar1 = base + (warp*4+1)*HIDD;
                    ar2 = base + (warp*4+2)*HIDD; ar3 = base + (warp*4+3)*HIDD;
                }

                #pragma unroll
                for (int kk = 0; kk < KT; ++kk) {
                    float wv0 = wb[kk*128       + lane];
                    float wv1 = wb[kk*128 +  32 + lane];
                    float wv2 = wb[kk*128 +  64 + lane];
                    float wv3 = wb[kk*128 +  96 + lane];
                    float a0 = ar0[kk], a1 = ar1[kk], a2 = ar2[kk], a3 = ar3[kk];
                    acc0[0] = fmaf(a0, wv0, acc0[0]); acc1[0] = fmaf(a0, wv1, acc1[0]);
                    acc2[0] = fmaf(a0, wv2, acc2[0]); acc3[0] = fmaf(a0, wv3, acc3[0]);
                    acc0[1] = fmaf(a1, wv0, acc0[1]); acc1[1] = fmaf(a1, wv1, acc1[1]);
                    acc2[1] = fmaf(a1, wv2, acc2[1]); acc3[1] = fmaf(a1, wv3, acc3[1]);
                    acc0[2] = fmaf(a2, wv0, acc0[2]); acc1[2] = fmaf(a2, wv1, acc1[2]);
                    acc2[2] = fmaf(a2, wv2, acc2[2]); acc3[2] = fmaf(a2, wv3, acc3[2]);
                    acc0[3] = fmaf(a3, wv0, acc0[3]); acc1[3] = fmaf(a3, wv1, acc1[3]);
                    acc2[3] = fmaf(a3, wv2, acc2[3]); acc3[3] = fmaf(a3, wv3, acc3[3]);
                }
            }

            // ---- LSTM cell update for this chunk's (word, hid) elements ----
            {
                int j = j0 + lane;
                #pragma unroll
                for (int wi = 0; wi < 4; ++wi) {
                    int w = warp*4 + wi;
                    float iv = fsigm(acc0[wi]);
                    float fv = fsigm(acc1[wi]);
                    float gv = ftanh_(acc2[wi]);
                    float ov = fsigm(acc3[wi]);
                    float cold = c_s[w*HIDD + j];
                    float cnew = fmaf(fv, cold, iv * gv);
                    float hnew = ov * ftanh_(cnew);
                    bool m = (t < len_s[w]);
                    c_s[w*HIDD + j] = m ? cnew : cold;
                    hn[w*HIDD + j]  = m ? hnew : hc[w*HIDD + j];
                }
            }
        }
        cur ^= 1;
        __syncthreads();
    }

    // ---- write final h (concat layout: [w, dir*256 + j]) ----
    const float* hf = h_s + cur*(BW*HIDD);
    for (int idx = tid; idx < BW*HIDD; idx += NTHREADS) {
        int w = idx >> 8, j = idx & 255;
        out[(w0 + w)*(2*HIDD) + dir*HIDD + j] = hf[idx];
    }
}

extern "C" void kernel_launch(void* const* d_in, const int* in_sizes, int n_in,
                              void* d_out, int out_size)
{
    const int*   char_ids = (const int*)  d_in[0];
    const int*   lengths  = (const int*)  d_in[1];
    const float* emb      = (const float*)d_in[2];
    const float* Wih_f    = (const float*)d_in[3];
    const float* Whh_f    = (const float*)d_in[4];
    const float* bih_f    = (const float*)d_in[5];
    const float* bhh_f    = (const float*)d_in[6];
    const float* Wih_b    = (const float*)d_in[7];
    const float* Whh_b    = (const float*)d_in[8];
    const float* bih_b    = (const float*)d_in[9];
    const float* bhh_b    = (const float*)d_in[10];
    float* out = (float*)d_out;

    cudaFuncSetAttribute(bilstm_kernel,
                         cudaFuncAttributeMaxDynamicSharedMemorySize, SMEM_BYTES);

    dim3 grid(NW / BW, 2);
    bilstm_kernel<<<grid, NTHREADS, SMEM_BYTES>>>(
        char_ids, lengths, emb,
        Wih_f, Whh_f, bih_f, bhh_f,
        Wih_b, Whh_b, bih_b, bhh_b,
        out);
}